// round 15
// baseline (speedup 1.0000x reference)
#include <cuda_runtime.h>
#include <math.h>
#include <stdint.h>

#define Bn  8
#define SQ  128
#define SK  128
#define IVD 32
#define DIM 32
#define EV  64
#define Hh  8
#define NH  128
#define DKd 8

#define ESS 136   // es row stride
#define HTS 20    // ht/et row stride

typedef unsigned long long u64;

// scratch (allocation-free rule: device globals)
__device__ float g_q[Bn*SQ*EV];
__device__ float g_k[Bn*SK*EV];
__device__ unsigned long long g_bar = 0;   // monotonic ticket barrier

__device__ __forceinline__ void cp_async16(uint32_t saddr, const void* gaddr) {
    asm volatile("cp.async.cg.shared.global [%0], [%1], 16;\n"
                 :: "r"(saddr), "l"(gaddr));
}
__device__ __forceinline__ void cp_commit() {
    asm volatile("cp.async.commit_group;\n");
}
__device__ __forceinline__ void cp_wait0() {
    asm volatile("cp.async.wait_group 0;\n");
}

__device__ __forceinline__ float fast_tanh(float x) {
    x = fminf(fmaxf(x, -15.f), 15.f);
    float e = __expf(2.f * x);
    return __fdividef(e - 1.f, e + 1.f);
}

// ---- packed fp32x2 (Blackwell FFMA2; per-lane IEEE fp32) ----
__device__ __forceinline__ u64 pack2(float lo, float hi) {
    u64 r; asm("mov.b64 %0, {%1, %2};" : "=l"(r) : "f"(lo), "f"(hi)); return r;
}
__device__ __forceinline__ void unpack2(u64 v, float& lo, float& hi) {
    asm("mov.b64 {%0, %1}, %2;" : "=f"(lo), "=f"(hi) : "l"(v));
}
__device__ __forceinline__ u64 fma2(u64 a, u64 b, u64 c) {
    u64 d; asm("fma.rn.f32x2 %0, %1, %2, %3;"
               : "=l"(d) : "l"(a), "l"(b), "l"(c)); return d;
}

// ---------------------------------------------------------------------------
// Single fused kernel. 256 blocks x 512 threads, 84KB dyn smem.
// 2 blocks/SM x 512 thr = 1024 thr/SM, 168KB smem/SM -> all 256 co-resident
// (grid barrier deadlock-free), 6.9 warps/SMSP (was 3.46).
//   Stage 1: blocks [0,128)   : proj, 16 rows/block
//            blocks [128,256) : impute MLP, 8 rows/block
//   Pre-barrier: ALL blocks load+convert value/mask -> mv/mf
//   grid barrier
//   Stage 2: attn block=(b, 4q, 8 heads) + fused out-GEMM epilogue.
// ---------------------------------------------------------------------------
extern __shared__ float as[];
__global__ void __launch_bounds__(512) mega_kernel(
    const float* __restrict__ qv, const float* __restrict__ kv,
    const float* __restrict__ value, const int* __restrict__ mask,
    const float* __restrict__ w1, const float* __restrict__ b1,
    const float* __restrict__ w2,
    const float* __restrict__ wq, const float* __restrict__ bq,
    const float* __restrict__ wk, const float* __restrict__ bk,
    const float* __restrict__ wo, const float* __restrict__ bo,
    const float* __restrict__ imp,
    const float* __restrict__ wd1, const float* __restrict__ bd1,
    const float* __restrict__ lng, const float* __restrict__ lnb,
    const float* __restrict__ wd2, const float* __restrict__ bd2,
    float* __restrict__ y_out, float* __restrict__ qd_out)
{
    int t   = threadIdx.x;
    int blk = blockIdx.x;

    int b  = blk >> 5;
    int q0 = (blk & 31) * 4;

    float* ks = as;              // 8192  (stage 2)
    float* qs = as + 8192;       // 256
    float* es = as + 8448;       // 4352 (32 rows x ESS)
    float* mv = as + 12800;      // 4096  (loaded pre-barrier)
    float* mf = as + 16896;      // 4096
    float* xs = as;              // 1024 overlay on ks after phase A

    if (blk < 128) {
        // ========== Stage 1a: proj, 16 rows/block ==========
        float* xs_t = as;            // [i][r] 32x16 transposed, 512 f
        float* ht   = as + 512;      // [p][r] 128xHTS transposed, 2560 f
        float* et   = as + 3072;     // [p][r] 64xHTS transposed, 1280 f
        float* ws2  = as + 4352;     // 8192 f

        int r0 = blk * 16;                     // row in [0,2048)
        bool isQ = r0 < Bn*SQ;
        int rr0 = isQ ? r0 : r0 - Bn*SQ;
        const float* xin = isQ ? qv : kv;
        const float* wp  = isQ ? wq : wk;
        const float* bp  = isQ ? bq : bk;
        float* outp      = isQ ? g_q : g_k;

        // stage w2 (latency hidden by phase 1)
        {
            uint32_t sb = (uint32_t)__cvta_generic_to_shared(ws2);
            #pragma unroll
            for (int j = 0; j < 4; j++) {
                int idx = t + j*512;           // 2048 float4s
                cp_async16(sb + idx*16, w2 + idx*4);
            }
            cp_commit();
        }

        // load 16 input rows, transposed [i][r]
        {
            int r = t >> 5, i = t & 31;        // 512 elements
            xs_t[i*16 + r] = xin[rr0*IVD + t];
        }
        __syncthreads();

        // phase 1: hidden. thread = (col c1 of 128, 4 rows), packed pairs
        {
            int c1  = t & 127;
            int rh1 = (t >> 7) * 4;            // 4 row-groups of 4
            float bb = b1[c1];
            u64 bb2 = pack2(bb, bb);
            u64 a01 = bb2, a23 = bb2;
            #pragma unroll
            for (int i = 0; i < IVD; i++) {
                float w = w1[i*NH + c1];
                u64 w2p = pack2(w, w);
                ulonglong2 x0 = *(const ulonglong2*)&xs_t[i*16 + rh1];
                a01 = fma2(x0.x, w2p, a01);
                a23 = fma2(x0.y, w2p, a23);
            }
            float v0,v1,v2,v3;
            unpack2(a01, v0, v1); unpack2(a23, v2, v3);
            float4 h0;
            h0.x = fast_tanh(v0); h0.y = fast_tanh(v1);
            h0.z = fast_tanh(v2); h0.w = fast_tanh(v3);
            *(float4*)&ht[c1*HTS + rh1] = h0;
        }
        cp_wait0();
        __syncthreads();

        int c  = t & 63;
        int rg = (t >> 6) * 2;        // 8 row-groups of 2

        // phase 2: embed (all-smem), packed
        {
            u64 a01 = 0;
            #pragma unroll 8
            for (int p = 0; p < NH; p++) {
                float w = ws2[p*EV + c];
                u64 w2p = pack2(w, w);
                u64 h2 = *(const u64*)&ht[p*HTS + rg];
                a01 = fma2(h2, w2p, a01);
            }
            float o0,o1;
            unpack2(a01, o0, o1);
            float2 o; o.x=o0; o.y=o1;
            *(float2*)&et[c*HTS + rg] = o;
        }
        __syncthreads();

        // phase 3: q/k projection, packed
        {
            float bb = bp[c];
            u64 bb2 = pack2(bb, bb);
            u64 a01 = bb2;
            #pragma unroll 8
            for (int p = 0; p < EV; p++) {
                float w = wp[p*EV + c];
                u64 w2p = pack2(w, w);
                u64 e2 = *(const u64*)&et[p*HTS + rg];
                a01 = fma2(e2, w2p, a01);
            }
            float o0,o1;
            unpack2(a01, o0, o1);
            outp[(rr0+rg+0)*EV + c] = o0;
            outp[(rr0+rg+1)*EV + c] = o1;
        }
    } else {
        // ========== Stage 1b: impute MLP, 8 rows/block, 512 thr ==========
        float* xi   = as;            // [8][16] 128 f
        float* htm  = as + 128;      // [128][8] transposed, 1024 f
        float* redS = as + 1152;     // 32 f (16 warps x 2 rows)
        float* redQ = as + 1184;     // 32 f

        int row0 = (blk - 128) * 8;
        if (t < 128) xi[t] = imp[row0*16 + t];
        __syncthreads();

        int c1   = t & 127;
        int g    = t >> 7;           // 0..3, rows base..base+1
        int base = g * 2;
        int w16  = t >> 5;           // warp 0..15
        int lane = t & 31;

        float a[2];
        {
            float bb = bd1[c1];
            a[0] = bb; a[1] = bb;
            #pragma unroll
            for (int i = 0; i < 16; i++) {
                float w = wd1[i*NH + c1];
                a[0] = fmaf(xi[(base+0)*16 + i], w, a[0]);
                a[1] = fmaf(xi[(base+1)*16 + i], w, a[1]);
            }
        }
        float ss0 = a[0], ss1 = a[1];
        float qq0 = a[0]*a[0], qq1 = a[1]*a[1];
        #pragma unroll
        for (int off = 16; off > 0; off >>= 1) {
            ss0 += __shfl_xor_sync(0xffffffff, ss0, off);
            ss1 += __shfl_xor_sync(0xffffffff, ss1, off);
            qq0 += __shfl_xor_sync(0xffffffff, qq0, off);
            qq1 += __shfl_xor_sync(0xffffffff, qq1, off);
        }
        if (lane == 0) {
            redS[w16*2+0] = ss0; redS[w16*2+1] = ss1;
            redQ[w16*2+0] = qq0; redQ[w16*2+1] = qq1;
        }
        __syncthreads();

        {
            float gg = lng[c1], be = lnb[c1];
            float2 hv; float* hp = (float*)&hv;
            #pragma unroll
            for (int j = 0; j < 2; j++) {
                float S = redS[(g*4+0)*2+j] + redS[(g*4+1)*2+j]
                        + redS[(g*4+2)*2+j] + redS[(g*4+3)*2+j];
                float Q = redQ[(g*4+0)*2+j] + redQ[(g*4+1)*2+j]
                        + redQ[(g*4+2)*2+j] + redQ[(g*4+3)*2+j];
                float mu  = S * (1.f/128.f);
                float var = Q * (1.f/128.f) - mu*mu;
                float ln = (a[j] - mu) * rsqrtf(var + 1e-5f) * gg + be;
                hp[j] = fmaxf(ln, 0.f);
            }
            *(float2*)&htm[c1*8 + base] = hv;
        }
        __syncthreads();

        // GEMM2, packed row pair
        {
            float bb = bd2[c1];
            u64 a01 = pack2(bb, bb);
            #pragma unroll 8
            for (int p = 0; p < NH; p++) {
                float w = wd2[p*NH + c1];
                u64 w2p = pack2(w, w);
                u64 h2 = *(const u64*)&htm[p*8 + base];
                a01 = fma2(h2, w2p, a01);
            }
            float o0,o1;
            unpack2(a01, o0, o1);
            qd_out[(row0+base+0)*NH + c1] = o0;
            qd_out[(row0+base+1)*NH + c1] = o1;
        }
    }

    // ===== pre-barrier: load + convert value/mask -> mv/mf =====
    __syncthreads();     // stage-1 smem reads done before mv/mf reuse
    {
        const float4* v4 = (const float4*)(value + b*SK*DIM);
        const int4*   m4 = (const int4*)  (mask  + b*SK*DIM);
        float4* mv4 = (float4*)mv;
        float4* mf4 = (float4*)mf;
        #pragma unroll
        for (int j = 0; j < 2; j++) {
            int idx = t + j*512;               // 1024 float4s
            int4 mm = m4[idx]; float4 vv = v4[idx];
            float4 av, af;
            av.x = mm.x ? vv.x : 0.f;  af.x = mm.x ? 1.f : 0.f;
            av.y = mm.y ? vv.y : 0.f;  af.y = mm.y ? 1.f : 0.f;
            av.z = mm.z ? vv.z : 0.f;  af.z = mm.z ? 1.f : 0.f;
            av.w = mm.w ? vv.w : 0.f;  af.w = mm.w ? 1.f : 0.f;
            mv4[idx] = av; mf4[idx] = af;
        }
    }

    // ================= grid barrier =================
    __threadfence();
    __syncthreads();
    if (t == 0) {
        unsigned long long ticket = atomicAdd(&g_bar, 1ULL);
        unsigned long long target = (ticket >> 8) * 256ULL + 256ULL;
        volatile unsigned long long* vb = &g_bar;
        while (*vb < target) { __nanosleep(64); }
        __threadfence();
    }
    __syncthreads();

    // ================= Stage 2: attn + out epilogue =================
    // load ks/qs (proj-dependent; via L2 to dodge stale-L1 across barrier)
    {
        const float4* gk4 = (const float4*)g_k;
        float4* ks4 = (float4*)ks;
        #pragma unroll
        for (int j = 0; j < 4; j++) {
            int idx = t + j*512;               // 2048 float4s
            ks4[idx] = __ldcg(&gk4[b*2048 + idx]);
        }
        if (t < 256) qs[t] = __ldcg(&g_q[(b*SQ + q0 + (t>>6))*EV + (t&63)]);
    }
    __syncthreads();

    const float scale = 0.35355339059327373f;   // 1/sqrt(8)

    // phase A: scores + softmax weights, packed dot products.
    // thread = (vr 0..31, kq 0..15): 8 k's each.
    {
        int vr = t >> 4;
        int q = vr >> 3, h = vr & 7;
        int kbase = (t & 15) * 8;
        float4 q0r = *(const float4*)&qs[q*EV + h*DKd];
        float4 q1r = *(const float4*)&qs[q*EV + h*DKd + 4];
        u64 qp0 = pack2(q0r.x, q0r.y);
        u64 qp1 = pack2(q0r.z, q0r.w);
        u64 qp2 = pack2(q1r.x, q1r.y);
        u64 qp3 = pack2(q1r.z, q1r.w);

        float s[8];
        #pragma unroll
        for (int i = 0; i < 8; i++) {
            const ulonglong2* kp = (const ulonglong2*)&ks[(kbase+i)*EV + h*DKd];
            ulonglong2 k0 = kp[0], k1 = kp[1];
            u64 a2 = fma2(qp0, k0.x, 0ULL);
            a2 = fma2(qp1, k0.y, a2);
            a2 = fma2(qp2, k1.x, a2);
            a2 = fma2(qp3, k1.y, a2);
            float lo, hi;
            unpack2(a2, lo, hi);
            s[i] = lo + hi;
        }
        float mx = s[0];
        #pragma unroll
        for (int i = 1; i < 8; i++) mx = fmaxf(mx, s[i]);
        // reduce across the 16 lanes sharing this vr (lane group of 16)
        mx = fmaxf(mx, __shfl_xor_sync(0xffffffff, mx, 1));
        mx = fmaxf(mx, __shfl_xor_sync(0xffffffff, mx, 2));
        mx = fmaxf(mx, __shfl_xor_sync(0xffffffff, mx, 4));
        mx = fmaxf(mx, __shfl_xor_sync(0xffffffff, mx, 8));
        float msc = mx * scale;
        #pragma unroll
        for (int i4 = 0; i4 < 2; i4++) {
            float4 ev;
            ev.x = __expf(fmaf(s[i4*4+0], scale, -msc));
            ev.y = __expf(fmaf(s[i4*4+1], scale, -msc));
            ev.z = __expf(fmaf(s[i4*4+2], scale, -msc));
            ev.w = __expf(fmaf(s[i4*4+3], scale, -msc));
            *(float4*)&es[vr*ESS + kbase + i4*4] = ev;
        }
    }
    __syncthreads();   // ks reads done -> xs overlay (on ks) safe below

    // phase B: num/den accumulate, packed. thread = (vr 0..31, ds 0..15):
    // 2 d's each via u64 loads.
    float2 xo;
    int vrB = t >> 4, dsB = t & 15;
    {
        u64 n01 = 0, d01 = 0;
        const u64* mv2 = (const u64*)mv;       // index k*16 + ds
        const u64* mf2 = (const u64*)mf;
        const float4* ep4 = (const float4*)&es[vrB*ESS];
        #pragma unroll 4
        for (int k4 = 0; k4 < SK/4; k4++) {
            float4 e4 = ep4[k4];
            #pragma unroll
            for (int j = 0; j < 4; j++) {
                float e = (j==0) ? e4.x : (j==1) ? e4.y : (j==2) ? e4.z : e4.w;
                int k = k4*4 + j;
                u64 e2 = pack2(e, e);
                n01 = fma2(e2, mv2[k*16 + dsB], n01);
                d01 = fma2(e2, mf2[k*16 + dsB], d01);
            }
        }
        float n0,n1, dd0,dd1;
        unpack2(n01, n0, n1);
        unpack2(d01, dd0, dd1);
        xo.x = __fdividef(n0, dd0); xo.y = __fdividef(n1, dd1);
    }
    {
        int q = vrB >> 3, h = vrB & 7;
        *(float2*)&xs[q*256 + h*DIM + dsB*2] = xo;
    }
    __syncthreads();

    // epilogue: y[q][c] = sum_p xs[q][p] * wo[p][c] + bo[c]
    // thread = (c 0..127, qsel 0..3): one output each; coalesced wo.
    {
        int c    = t & 127;
        int qsel = t >> 7;            // 0..3
        float acc = bo[c];
        const float* xp = &xs[qsel*256];
        #pragma unroll 8
        for (int p = 0; p < 256; p++)
            acc = fmaf(xp[p], wo[p*NH + c], acc);
        y_out[(b*SQ + q0 + qsel)*NH + c] = acc;
    }
}

// ---------------------------------------------------------------------------
extern "C" void kernel_launch(void* const* d_in, const int* in_sizes, int n_in,
                              void* d_out, int out_size)
{
    bool dictOrder = (in_sizes[4] == Bn*SK*DIM);

    const float *qv, *kv, *val, *imp, *w1, *b1, *w2, *wq, *bq, *wk, *bk,
                *wo, *bo, *wd1, *bd1, *lng, *lnb, *wd2, *bd2;
    const int* mask;

    if (dictOrder) {
        qv  = (const float*)d_in[0];  kv  = (const float*)d_in[1];
        val = (const float*)d_in[2];  imp = (const float*)d_in[3];
        mask= (const int*)  d_in[4];
        w1  = (const float*)d_in[5];  b1  = (const float*)d_in[6];
        w2  = (const float*)d_in[7];
        wq  = (const float*)d_in[8];  bq  = (const float*)d_in[9];
        wk  = (const float*)d_in[10]; bk  = (const float*)d_in[11];
        wo  = (const float*)d_in[12]; bo  = (const float*)d_in[13];
        wd1 = (const float*)d_in[14]; bd1 = (const float*)d_in[15];
        lng = (const float*)d_in[16]; lnb = (const float*)d_in[17];
        wd2 = (const float*)d_in[18]; bd2 = (const float*)d_in[19];
    } else {
        qv  = (const float*)d_in[0];  kv  = (const float*)d_in[1];
        val = (const float*)d_in[2];  imp = (const float*)d_in[3];
        w1  = (const float*)d_in[4];  b1  = (const float*)d_in[5];
        w2  = (const float*)d_in[6];
        wq  = (const float*)d_in[7];  bq  = (const float*)d_in[8];
        wk  = (const float*)d_in[9];  bk  = (const float*)d_in[10];
        wo  = (const float*)d_in[11]; bo  = (const float*)d_in[12];
        wd1 = (const float*)d_in[13]; bd1 = (const float*)d_in[14];
        lng = (const float*)d_in[15]; lnb = (const float*)d_in[16];
        wd2 = (const float*)d_in[17]; bd2 = (const float*)d_in[18];
        mask= (const int*)  d_in[19];
    }

    float* y  = (float*)d_out;                       // [8,128,128]
    float* qd = (float*)d_out + Bn*SQ*NH;            // [8,128,128]

    cudaFuncSetAttribute(mega_kernel,
                         cudaFuncAttributeMaxDynamicSharedMemorySize,
                         20992 * sizeof(float));

    mega_kernel<<<256, 512, 20992 * sizeof(float)>>>(
        qv, kv, val, mask, w1, b1, w2, wq, bq, wk, bk, wo, bo,
        imp, wd1, bd1, lng, lnb, wd2, bd2, y, qd);
}

// round 16
// speedup vs baseline: 1.0264x; 1.0264x over previous
#include <cuda_runtime.h>
#include <math.h>
#include <stdint.h>

#define Bn  8
#define SQ  128
#define SK  128
#define IVD 32
#define DIM 32
#define EV  64
#define Hh  8
#define NH  128
#define DKd 8

#define ESS 136   // es row stride (conflict-breaking pad)
#define HTS 20    // ht/et row stride (conflict-breaking pad)

typedef unsigned long long u64;

// scratch (allocation-free rule: device globals)
__device__ float g_q[Bn*SQ*EV];
__device__ float g_k[Bn*SK*EV];
__device__ unsigned long long g_bar = 0;   // monotonic ticket barrier

__device__ __forceinline__ void cp_async16(uint32_t saddr, const void* gaddr) {
    asm volatile("cp.async.cg.shared.global [%0], [%1], 16;\n"
                 :: "r"(saddr), "l"(gaddr));
}
__device__ __forceinline__ void cp_commit() {
    asm volatile("cp.async.commit_group;\n");
}
__device__ __forceinline__ void cp_wait0() {
    asm volatile("cp.async.wait_group 0;\n");
}

__device__ __forceinline__ float fast_tanh(float x) {
    x = fminf(fmaxf(x, -15.f), 15.f);
    float e = __expf(2.f * x);
    return __fdividef(e - 1.f, e + 1.f);
}

// ---- packed fp32x2 (Blackwell FFMA2; per-lane IEEE fp32) ----
__device__ __forceinline__ u64 pack2(float lo, float hi) {
    u64 r; asm("mov.b64 %0, {%1, %2};" : "=l"(r) : "f"(lo), "f"(hi)); return r;
}
__device__ __forceinline__ void unpack2(u64 v, float& lo, float& hi) {
    asm("mov.b64 {%0, %1}, %2;" : "=f"(lo), "=f"(hi) : "l"(v));
}
__device__ __forceinline__ u64 fma2(u64 a, u64 b, u64 c) {
    u64 d; asm("fma.rn.f32x2 %0, %1, %2, %3;"
               : "=l"(d) : "l"(a), "l"(b), "l"(c)); return d;
}

// ---------------------------------------------------------------------------
// Single fused kernel. 256 blocks x 256 threads, 84KB dyn smem (2 blocks/SM
// capacity -> all 256 co-resident -> grid barrier deadlock-free).
//   Stage 1: blocks [0,128)   : proj, 16 rows/block
//            blocks [128,256) : impute MLP, 8 rows/block
//   Pre-barrier: ALL blocks load+convert value/mask -> mv/mf
//   grid barrier
//   Stage 2: attn block=(b, 4q, 8 heads) + fused out-GEMM epilogue.
// Phase A simplification: no max-subtraction (out = num/den is invariant to
// the exp rescale; raw scores are tanh-bounded so no overflow) -> removes
// the serialized shuffle-max chain and lets exp overlap dot products.
// ---------------------------------------------------------------------------
extern __shared__ float as[];
__global__ void __launch_bounds__(256) mega_kernel(
    const float* __restrict__ qv, const float* __restrict__ kv,
    const float* __restrict__ value, const int* __restrict__ mask,
    const float* __restrict__ w1, const float* __restrict__ b1,
    const float* __restrict__ w2,
    const float* __restrict__ wq, const float* __restrict__ bq,
    const float* __restrict__ wk, const float* __restrict__ bk,
    const float* __restrict__ wo, const float* __restrict__ bo,
    const float* __restrict__ imp,
    const float* __restrict__ wd1, const float* __restrict__ bd1,
    const float* __restrict__ lng, const float* __restrict__ lnb,
    const float* __restrict__ wd2, const float* __restrict__ bd2,
    float* __restrict__ y_out, float* __restrict__ qd_out)
{
    int t   = threadIdx.x;
    int blk = blockIdx.x;

    int b  = blk >> 5;
    int q0 = (blk & 31) * 4;

    float* ks = as;              // 8192  (stage 2)
    float* qs = as + 8192;       // 256
    float* es = as + 8448;       // 4352 (32 rows x ESS)
    float* mv = as + 12800;      // 4096  (loaded pre-barrier)
    float* mf = as + 16896;      // 4096
    float* xs = as;              // 1024 overlay on ks after phase A

    if (blk < 128) {
        // ========== Stage 1a: proj, 16 rows/block ==========
        float* xs_t = as;            // [i][r] 32x16 transposed, 512 f
        float* ht   = as + 512;      // [p][r] 128xHTS transposed, 2560 f
        float* et   = as + 3072;     // [p][r] 64xHTS transposed, 1280 f
        float* ws2  = as + 4352;     // 8192 f (ends at 12544 < 12800)

        int r0 = blk * 16;                     // row in [0,2048)
        bool isQ = r0 < Bn*SQ;
        int rr0 = isQ ? r0 : r0 - Bn*SQ;
        const float* xin = isQ ? qv : kv;
        const float* wp  = isQ ? wq : wk;
        const float* bp  = isQ ? bq : bk;
        float* outp      = isQ ? g_q : g_k;

        // stage w2 (latency hidden by phase 1)
        {
            uint32_t sb = (uint32_t)__cvta_generic_to_shared(ws2);
            #pragma unroll
            for (int j = 0; j < 8; j++) {
                int idx = t + j*256;           // 2048 float4s
                cp_async16(sb + idx*16, w2 + idx*4);
            }
            cp_commit();
        }

        // load 16 input rows, transposed [i][r]
        #pragma unroll
        for (int j = 0; j < 2; j++) {
            int idx = t + j*256;               // 0..511
            int r = idx >> 5, i = idx & 31;
            xs_t[i*16 + r] = xin[rr0*IVD + idx];
        }
        __syncthreads();

        // phase 1: hidden. thread = (col c1 of 128, 8 rows), packed pairs
        {
            int c1  = t & 127;
            int rh1 = (t >> 7) * 8;
            float bb = b1[c1];
            u64 bb2 = pack2(bb, bb);
            u64 a01 = bb2, a23 = bb2, a45 = bb2, a67 = bb2;
            #pragma unroll
            for (int i = 0; i < IVD; i++) {
                float w = w1[i*NH + c1];
                u64 w2p = pack2(w, w);
                ulonglong2 x0 = *(const ulonglong2*)&xs_t[i*16 + rh1];
                ulonglong2 x1 = *(const ulonglong2*)&xs_t[i*16 + rh1 + 4];
                a01 = fma2(x0.x, w2p, a01);
                a23 = fma2(x0.y, w2p, a23);
                a45 = fma2(x1.x, w2p, a45);
                a67 = fma2(x1.y, w2p, a67);
            }
            float v0,v1,v2,v3,v4,v5,v6,v7;
            unpack2(a01, v0, v1); unpack2(a23, v2, v3);
            unpack2(a45, v4, v5); unpack2(a67, v6, v7);
            float4 h0, h1;
            h0.x = fast_tanh(v0); h0.y = fast_tanh(v1);
            h0.z = fast_tanh(v2); h0.w = fast_tanh(v3);
            h1.x = fast_tanh(v4); h1.y = fast_tanh(v5);
            h1.z = fast_tanh(v6); h1.w = fast_tanh(v7);
            *(float4*)&ht[c1*HTS + rh1]     = h0;
            *(float4*)&ht[c1*HTS + rh1 + 4] = h1;
        }
        cp_wait0();
        __syncthreads();

        int c  = t & 63;
        int rg = (t >> 6) * 4;        // rows rg..rg+3

        // phase 2: embed (all-smem), packed
        {
            u64 a01 = 0, a23 = 0;
            #pragma unroll 8
            for (int p = 0; p < NH; p++) {
                float w = ws2[p*EV + c];
                u64 w2p = pack2(w, w);
                ulonglong2 h = *(const ulonglong2*)&ht[p*HTS + rg];
                a01 = fma2(h.x, w2p, a01);
                a23 = fma2(h.y, w2p, a23);
            }
            float o0,o1,o2,o3;
            unpack2(a01, o0, o1); unpack2(a23, o2, o3);
            float4 o; o.x=o0; o.y=o1; o.z=o2; o.w=o3;
            *(float4*)&et[c*HTS + rg] = o;
        }
        __syncthreads();

        // phase 3: q/k projection, packed
        {
            float bb = bp[c];
            u64 bb2 = pack2(bb, bb);
            u64 a01 = bb2, a23 = bb2;
            #pragma unroll 8
            for (int p = 0; p < EV; p++) {
                float w = wp[p*EV + c];
                u64 w2p = pack2(w, w);
                ulonglong2 e = *(const ulonglong2*)&et[p*HTS + rg];
                a01 = fma2(e.x, w2p, a01);
                a23 = fma2(e.y, w2p, a23);
            }
            float o0,o1,o2,o3;
            unpack2(a01, o0, o1); unpack2(a23, o2, o3);
            outp[(rr0+rg+0)*EV + c] = o0;
            outp[(rr0+rg+1)*EV + c] = o1;
            outp[(rr0+rg+2)*EV + c] = o2;
            outp[(rr0+rg+3)*EV + c] = o3;
        }
    } else {
        // ========== Stage 1b: impute MLP, 8 rows/block ==========
        float* xi   = as;            // [8][16] 128 f
        float* htm  = as + 128;      // [128][8] transposed, 1024 f
        float* redS = as + 1152;     // 32 f
        float* redQ = as + 1184;     // 32 f

        int row0 = (blk - 128) * 8;
        if (t < 128) xi[t] = imp[row0*16 + t];
        __syncthreads();

        int c1   = t & 127;
        int base = (t >> 7) * 4;     // rows base..base+3
        int w8   = t >> 5;
        int lane = t & 31;

        float a[4];
        {
            float bb = bd1[c1];
            #pragma unroll
            for (int j = 0; j < 4; j++) a[j] = bb;
            #pragma unroll
            for (int i = 0; i < 16; i++) {
                float w = wd1[i*NH + c1];
                #pragma unroll
                for (int j = 0; j < 4; j++)
                    a[j] = fmaf(xi[(base+j)*16 + i], w, a[j]);
            }
        }
        float ss[4], qq[4];
        #pragma unroll
        for (int j = 0; j < 4; j++) { ss[j] = a[j]; qq[j] = a[j]*a[j]; }
        #pragma unroll
        for (int off = 16; off > 0; off >>= 1) {
            #pragma unroll
            for (int j = 0; j < 4; j++) {
                ss[j] += __shfl_xor_sync(0xffffffff, ss[j], off);
                qq[j] += __shfl_xor_sync(0xffffffff, qq[j], off);
            }
        }
        if (lane == 0) {
            #pragma unroll
            for (int j = 0; j < 4; j++) { redS[w8*4+j] = ss[j]; redQ[w8*4+j] = qq[j]; }
        }
        __syncthreads();

        float g = lng[c1], be = lnb[c1];
        int gw = (base == 0) ? 0 : 4;
        {
            float4 hv; float* hp = (float*)&hv;
            #pragma unroll
            for (int j = 0; j < 4; j++) {
                float S = redS[(gw+0)*4+j] + redS[(gw+1)*4+j]
                        + redS[(gw+2)*4+j] + redS[(gw+3)*4+j];
                float Q = redQ[(gw+0)*4+j] + redQ[(gw+1)*4+j]
                        + redQ[(gw+2)*4+j] + redQ[(gw+3)*4+j];
                float mu  = S * (1.f/128.f);
                float var = Q * (1.f/128.f) - mu*mu;
                float ln = (a[j] - mu) * rsqrtf(var + 1e-5f) * g + be;
                hp[j] = fmaxf(ln, 0.f);
            }
            *(float4*)&htm[c1*8 + base] = hv;
        }
        __syncthreads();

        // GEMM2, packed row pairs
        {
            float bb = bd2[c1];
            u64 bb2 = pack2(bb, bb);
            u64 a01 = bb2, a23 = bb2;
            #pragma unroll 8
            for (int p = 0; p < NH; p++) {
                float w = wd2[p*NH + c1];
                u64 w2p = pack2(w, w);
                ulonglong2 h = *(const ulonglong2*)&htm[p*8 + base];
                a01 = fma2(h.x, w2p, a01);
                a23 = fma2(h.y, w2p, a23);
            }
            float o0,o1,o2,o3;
            unpack2(a01, o0, o1); unpack2(a23, o2, o3);
            qd_out[(row0+base+0)*NH + c1] = o0;
            qd_out[(row0+base+1)*NH + c1] = o1;
            qd_out[(row0+base+2)*NH + c1] = o2;
            qd_out[(row0+base+3)*NH + c1] = o3;
        }
    }

    // ===== pre-barrier: load + convert value/mask -> mv/mf =====
    __syncthreads();     // stage-1 smem reads done before any mv/mf reuse
    {
        const float4* v4 = (const float4*)(value + b*SK*DIM);
        const int4*   m4 = (const int4*)  (mask  + b*SK*DIM);
        float4* mv4 = (float4*)mv;
        float4* mf4 = (float4*)mf;
        #pragma unroll
        for (int j = 0; j < 4; j++) {
            int idx = t + j*256;               // 1024 float4s
            int4 mm = m4[idx]; float4 vv = v4[idx];
            float4 av, af;
            av.x = mm.x ? vv.x : 0.f;  af.x = mm.x ? 1.f : 0.f;
            av.y = mm.y ? vv.y : 0.f;  af.y = mm.y ? 1.f : 0.f;
            av.z = mm.z ? vv.z : 0.f;  af.z = mm.z ? 1.f : 0.f;
            av.w = mm.w ? vv.w : 0.f;  af.w = mm.w ? 1.f : 0.f;
            mv4[idx] = av; mf4[idx] = af;
        }
    }

    // ================= grid barrier =================
    __threadfence();
    __syncthreads();
    if (t == 0) {
        unsigned long long ticket = atomicAdd(&g_bar, 1ULL);
        unsigned long long target = (ticket >> 8) * 256ULL + 256ULL;
        volatile unsigned long long* vb = &g_bar;
        while (*vb < target) { __nanosleep(64); }
        __threadfence();
    }
    __syncthreads();

    // ================= Stage 2: attn + out epilogue =================
    // load ks/qs (proj-dependent; via L2 to dodge stale-L1 across barrier)
    {
        const float4* gk4 = (const float4*)g_k;
        float4* ks4 = (float4*)ks;
        #pragma unroll
        for (int j = 0; j < 8; j++) {
            int idx = t + j*256;               // 2048 float4s
            ks4[idx] = __ldcg(&gk4[b*2048 + idx]);
        }
        qs[t] = __ldcg(&g_q[(b*SQ + q0 + (t>>6))*EV + (t&63)]);
    }
    __syncthreads();

    const float scale = 0.35355339059327373f;   // 1/sqrt(8)

    // phase A: e = exp(q·k/sqrt(8)) directly -- NO max subtraction
    // (num/den invariant; tanh-bounded scores cannot overflow fp32).
    // q pre-scaled at pack time. warp = head mapping (ks reads dedup 4x).
    {
        int h  = t >> 5;
        int q  = (t >> 3) & 3;
        int kq = t & 7;
        int vr = q*8 + h;             // es row convention unchanged
        int kbase = kq * 16;
        float4 q0r = *(const float4*)&qs[q*EV + h*DKd];
        float4 q1r = *(const float4*)&qs[q*EV + h*DKd + 4];
        u64 qp0 = pack2(q0r.x*scale, q0r.y*scale);
        u64 qp1 = pack2(q0r.z*scale, q0r.w*scale);
        u64 qp2 = pack2(q1r.x*scale, q1r.y*scale);
        u64 qp3 = pack2(q1r.z*scale, q1r.w*scale);

        #pragma unroll
        for (int i4 = 0; i4 < 4; i4++) {
            float4 ev;
            float* ep = (float*)&ev;
            #pragma unroll
            for (int j = 0; j < 4; j++) {
                int i = i4*4 + j;
                const ulonglong2* kp =
                    (const ulonglong2*)&ks[(kbase+i)*EV + h*DKd];
                ulonglong2 k0 = kp[0], k1 = kp[1];
                u64 a2 = fma2(qp0, k0.x, 0ULL);
                a2 = fma2(qp1, k0.y, a2);
                a2 = fma2(qp2, k1.x, a2);
                a2 = fma2(qp3, k1.y, a2);
                float lo, hi;
                unpack2(a2, lo, hi);
                ep[j] = __expf(lo + hi);
            }
            *(float4*)&es[vr*ESS + kbase + i4*4] = ev;
        }
    }
    __syncthreads();   // ks reads done -> xs overlay (on ks) is safe below

    // phase B: num/den accumulate, packed. vr 0..31, dq 0..7 (4 d each)
    float4 xo;
    int vrB = t >> 3, dqB = t & 7;
    {
        u64 n01 = 0, n23 = 0, d01 = 0, d23 = 0;
        const ulonglong2* mv2 = (const ulonglong2*)mv;
        const ulonglong2* mf2 = (const ulonglong2*)mf;
        const float4* ep4 = (const float4*)&es[vrB*ESS];
        #pragma unroll 4
        for (int k4 = 0; k4 < SK/4; k4++) {
            float4 e4 = ep4[k4];
            #pragma unroll
            for (int j = 0; j < 4; j++) {
                float e = (j==0) ? e4.x : (j==1) ? e4.y : (j==2) ? e4.z : e4.w;
                int k = k4*4 + j;
                u64 e2 = pack2(e, e);
                ulonglong2 v = mv2[k*8 + dqB];
                ulonglong2 m = mf2[k*8 + dqB];
                n01 = fma2(e2, v.x, n01);
                n23 = fma2(e2, v.y, n23);
                d01 = fma2(e2, m.x, d01);
                d23 = fma2(e2, m.y, d23);
            }
        }
        float n0,n1,n2,n3, dd0,dd1,dd2,dd3;
        unpack2(n01, n0, n1); unpack2(n23, n2, n3);
        unpack2(d01, dd0, dd1); unpack2(d23, dd2, dd3);
        xo.x = __fdividef(n0, dd0); xo.y = __fdividef(n1, dd1);
        xo.z = __fdividef(n2, dd2); xo.w = __fdividef(n3, dd3);
    }
    {
        int q = vrB >> 3, h = vrB & 7;
        *(float4*)&xs[q*256 + h*DIM + dqB*4] = xo;
    }
    __syncthreads();

    // epilogue: y[q][c] = sum_p xs[q][p] * wo[p][c] + bo[c]
    // thread = (col pair cp, row qsel); packed col-pair FMA, LDG.64 wo.
    {
        int cp   = (t & 63) * 2;
        int qsel = t >> 6;            // 0..3
        u64 acc = pack2(bo[cp], bo[cp+1]);
        const float* xp = &xs[qsel*256];
        #pragma unroll 8
        for (int p = 0; p < 256; p++) {
            u64 w2p = *(const u64*)&wo[p*NH + cp];
            u64 x2  = pack2(xp[p], xp[p]);
            acc = fma2(x2, w2p, acc);
        }
        float r0v, r1v;
        unpack2(acc, r0v, r1v);
        float2 o; o.x = r0v; o.y = r1v;
        *(float2*)&y_out[(b*SQ + q0 + qsel)*NH + cp] = o;
    }
}

// ---------------------------------------------------------------------------
extern "C" void kernel_launch(void* const* d_in, const int* in_sizes, int n_in,
                              void* d_out, int out_size)
{
    bool dictOrder = (in_sizes[4] == Bn*SK*DIM);

    const float *qv, *kv, *val, *imp, *w1, *b1, *w2, *wq, *bq, *wk, *bk,
                *wo, *bo, *wd1, *bd1, *lng, *lnb, *wd2, *bd2;
    const int* mask;

    if (dictOrder) {
        qv  = (const float*)d_in[0];  kv  = (const float*)d_in[1];
        val = (const float*)d_in[2];  imp = (const float*)d_in[3];
        mask= (const int*)  d_in[4];
        w1  = (const float*)d_in[5];  b1  = (const float*)d_in[6];
        w2  = (const float*)d_in[7];
        wq  = (const float*)d_in[8];  bq  = (const float*)d_in[9];
        wk  = (const float*)d_in[10]; bk  = (const float*)d_in[11];
        wo  = (const float*)d_in[12]; bo  = (const float*)d_in[13];
        wd1 = (const float*)d_in[14]; bd1 = (const float*)d_in[15];
        lng = (const float*)d_in[16]; lnb = (const float*)d_in[17];
        wd2 = (const float*)d_in[18]; bd2 = (const float*)d_in[19];
    } else {
        qv  = (const float*)d_in[0];  kv  = (const float*)d_in[1];
        val = (const float*)d_in[2];  imp = (const float*)d_in[3];
        w1  = (const float*)d_in[4];  b1  = (const float*)d_in[5];
        w2  = (const float*)d_in[6];
        wq  = (const float*)d_in[7];  bq  = (const float*)d_in[8];
        wk  = (const float*)d_in[9];  bk  = (const float*)d_in[10];
        wo  = (const float*)d_in[11]; bo  = (const float*)d_in[12];
        wd1 = (const float*)d_in[13]; bd1 = (const float*)d_in[14];
        lng = (const float*)d_in[15]; lnb = (const float*)d_in[16];
        wd2 = (const float*)d_in[17]; bd2 = (const float*)d_in[18];
        mask= (const int*)  d_in[19];
    }

    float* y  = (float*)d_out;                       // [8,128,128]
    float* qd = (float*)d_out + Bn*SQ*NH;            // [8,128,128]

    cudaFuncSetAttribute(mega_kernel,
                         cudaFuncAttributeMaxDynamicSharedMemorySize,
                         20992 * sizeof(float));

    mega_kernel<<<256, 256, 20992 * sizeof(float)>>>(
        qv, kv, val, mask, w1, b1, w2, wq, bq, wk, bk, wo, bo,
        imp, wd1, bd1, lng, lnb, wd2, bd2, y, qd);
}

// round 17
// speedup vs baseline: 1.2014x; 1.1705x over previous
#include <cuda_runtime.h>
#include <math.h>
#include <stdint.h>

#define Bn  8
#define SQ  128
#define SK  128
#define IVD 32
#define DIM 32
#define EV  64
#define Hh  8
#define NH  128
#define DKd 8

#define ESS 136   // es row stride (conflict-breaking pad)
#define HTS 20    // ht/et row stride (conflict-breaking pad)

typedef unsigned long long u64;

// scratch (allocation-free rule: device globals)
__device__ float g_q[Bn*SQ*EV];
__device__ float g_k[Bn*SK*EV];
__device__ unsigned long long g_bar = 0;   // monotonic ticket barrier

__device__ __forceinline__ void cp_async16(uint32_t saddr, const void* gaddr) {
    asm volatile("cp.async.cg.shared.global [%0], [%1], 16;\n"
                 :: "r"(saddr), "l"(gaddr));
}
__device__ __forceinline__ void cp_commit() {
    asm volatile("cp.async.commit_group;\n");
}
__device__ __forceinline__ void cp_wait0() {
    asm volatile("cp.async.wait_group 0;\n");
}

__device__ __forceinline__ float fast_tanh(float x) {
    x = fminf(fmaxf(x, -15.f), 15.f);
    float e = __expf(2.f * x);
    return __fdividef(e - 1.f, e + 1.f);
}

// ---- packed fp32x2 (Blackwell FFMA2; per-lane IEEE fp32) ----
__device__ __forceinline__ u64 pack2(float lo, float hi) {
    u64 r; asm("mov.b64 %0, {%1, %2};" : "=l"(r) : "f"(lo), "f"(hi)); return r;
}
__device__ __forceinline__ void unpack2(u64 v, float& lo, float& hi) {
    asm("mov.b64 {%0, %1}, %2;" : "=f"(lo), "=f"(hi) : "l"(v));
}
__device__ __forceinline__ u64 fma2(u64 a, u64 b, u64 c) {
    u64 d; asm("fma.rn.f32x2 %0, %1, %2, %3;"
               : "=l"(d) : "l"(a), "l"(b), "l"(c)); return d;
}
__device__ __forceinline__ u64 add2(u64 a, u64 b) {
    u64 d; asm("add.rn.f32x2 %0, %1, %2;" : "=l"(d) : "l"(a), "l"(b)); return d;
}

// ---------------------------------------------------------------------------
// Single fused kernel. 256 blocks x 256 threads, 84KB dyn smem (2 blocks/SM
// capacity -> all 256 co-resident -> grid barrier deadlock-free).
//   Stage 1: blocks [0,128)   : proj, 16 rows/block
//            blocks [128,256) : impute MLP, 8 rows/block
//   Pre-barrier: ALL blocks load+convert value/mask -> mv/mf
//   grid barrier
//   Stage 2: attn block=(b, 4q, 8 heads) + fused out-GEMM epilogue.
// Epilogue: 2 independent chains over p-halves, unroll 32 -> deep wo-LDG
// pipeline (the largest remaining exposed-latency window).
// ---------------------------------------------------------------------------
extern __shared__ float as[];
__global__ void __launch_bounds__(256, 2) mega_kernel(
    const float* __restrict__ qv, const float* __restrict__ kv,
    const float* __restrict__ value, const int* __restrict__ mask,
    const float* __restrict__ w1, const float* __restrict__ b1,
    const float* __restrict__ w2,
    const float* __restrict__ wq, const float* __restrict__ bq,
    const float* __restrict__ wk, const float* __restrict__ bk,
    const float* __restrict__ wo, const float* __restrict__ bo,
    const float* __restrict__ imp,
    const float* __restrict__ wd1, const float* __restrict__ bd1,
    const float* __restrict__ lng, const float* __restrict__ lnb,
    const float* __restrict__ wd2, const float* __restrict__ bd2,
    float* __restrict__ y_out, float* __restrict__ qd_out)
{
    int t   = threadIdx.x;
    int blk = blockIdx.x;

    int b  = blk >> 5;
    int q0 = (blk & 31) * 4;

    float* ks = as;              // 8192  (stage 2)
    float* qs = as + 8192;       // 256
    float* es = as + 8448;       // 4352 (32 rows x ESS)
    float* mv = as + 12800;      // 4096  (loaded pre-barrier)
    float* mf = as + 16896;      // 4096
    float* xs = as;              // 1024 overlay on ks after phase A

    if (blk < 128) {
        // ========== Stage 1a: proj, 16 rows/block ==========
        float* xs_t = as;            // [i][r] 32x16 transposed, 512 f
        float* ht   = as + 512;      // [p][r] 128xHTS transposed, 2560 f
        float* et   = as + 3072;     // [p][r] 64xHTS transposed, 1280 f
        float* ws2  = as + 4352;     // 8192 f (ends at 12544 < 12800)

        int r0 = blk * 16;                     // row in [0,2048)
        bool isQ = r0 < Bn*SQ;
        int rr0 = isQ ? r0 : r0 - Bn*SQ;
        const float* xin = isQ ? qv : kv;
        const float* wp  = isQ ? wq : wk;
        const float* bp  = isQ ? bq : bk;
        float* outp      = isQ ? g_q : g_k;

        // stage w2 (latency hidden by phase 1)
        {
            uint32_t sb = (uint32_t)__cvta_generic_to_shared(ws2);
            #pragma unroll
            for (int j = 0; j < 8; j++) {
                int idx = t + j*256;           // 2048 float4s
                cp_async16(sb + idx*16, w2 + idx*4);
            }
            cp_commit();
        }

        // load 16 input rows, transposed [i][r]
        #pragma unroll
        for (int j = 0; j < 2; j++) {
            int idx = t + j*256;               // 0..511
            int r = idx >> 5, i = idx & 31;
            xs_t[i*16 + r] = xin[rr0*IVD + idx];
        }
        __syncthreads();

        // phase 1: hidden. thread = (col c1 of 128, 8 rows), packed pairs
        {
            int c1  = t & 127;
            int rh1 = (t >> 7) * 8;
            float bb = b1[c1];
            u64 bb2 = pack2(bb, bb);
            u64 a01 = bb2, a23 = bb2, a45 = bb2, a67 = bb2;
            #pragma unroll
            for (int i = 0; i < IVD; i++) {
                float w = w1[i*NH + c1];
                u64 w2p = pack2(w, w);
                ulonglong2 x0 = *(const ulonglong2*)&xs_t[i*16 + rh1];
                ulonglong2 x1 = *(const ulonglong2*)&xs_t[i*16 + rh1 + 4];
                a01 = fma2(x0.x, w2p, a01);
                a23 = fma2(x0.y, w2p, a23);
                a45 = fma2(x1.x, w2p, a45);
                a67 = fma2(x1.y, w2p, a67);
            }
            float v0,v1,v2,v3,v4,v5,v6,v7;
            unpack2(a01, v0, v1); unpack2(a23, v2, v3);
            unpack2(a45, v4, v5); unpack2(a67, v6, v7);
            float4 h0, h1;
            h0.x = fast_tanh(v0); h0.y = fast_tanh(v1);
            h0.z = fast_tanh(v2); h0.w = fast_tanh(v3);
            h1.x = fast_tanh(v4); h1.y = fast_tanh(v5);
            h1.z = fast_tanh(v6); h1.w = fast_tanh(v7);
            *(float4*)&ht[c1*HTS + rh1]     = h0;
            *(float4*)&ht[c1*HTS + rh1 + 4] = h1;
        }
        cp_wait0();
        __syncthreads();

        int c  = t & 63;
        int rg = (t >> 6) * 4;        // rows rg..rg+3

        // phase 2: embed (all-smem), packed
        {
            u64 a01 = 0, a23 = 0;
            #pragma unroll 8
            for (int p = 0; p < NH; p++) {
                float w = ws2[p*EV + c];
                u64 w2p = pack2(w, w);
                ulonglong2 h = *(const ulonglong2*)&ht[p*HTS + rg];
                a01 = fma2(h.x, w2p, a01);
                a23 = fma2(h.y, w2p, a23);
            }
            float o0,o1,o2,o3;
            unpack2(a01, o0, o1); unpack2(a23, o2, o3);
            float4 o; o.x=o0; o.y=o1; o.z=o2; o.w=o3;
            *(float4*)&et[c*HTS + rg] = o;
        }
        __syncthreads();

        // phase 3: q/k projection, packed
        {
            float bb = bp[c];
            u64 bb2 = pack2(bb, bb);
            u64 a01 = bb2, a23 = bb2;
            #pragma unroll 8
            for (int p = 0; p < EV; p++) {
                float w = wp[p*EV + c];
                u64 w2p = pack2(w, w);
                ulonglong2 e = *(const ulonglong2*)&et[p*HTS + rg];
                a01 = fma2(e.x, w2p, a01);
                a23 = fma2(e.y, w2p, a23);
            }
            float o0,o1,o2,o3;
            unpack2(a01, o0, o1); unpack2(a23, o2, o3);
            outp[(rr0+rg+0)*EV + c] = o0;
            outp[(rr0+rg+1)*EV + c] = o1;
            outp[(rr0+rg+2)*EV + c] = o2;
            outp[(rr0+rg+3)*EV + c] = o3;
        }
    } else {
        // ========== Stage 1b: impute MLP, 8 rows/block ==========
        float* xi   = as;            // [8][16] 128 f
        float* htm  = as + 128;      // [128][8] transposed, 1024 f
        float* redS = as + 1152;     // 32 f
        float* redQ = as + 1184;     // 32 f

        int row0 = (blk - 128) * 8;
        if (t < 128) xi[t] = imp[row0*16 + t];
        __syncthreads();

        int c1   = t & 127;
        int base = (t >> 7) * 4;     // rows base..base+3
        int w8   = t >> 5;
        int lane = t & 31;

        float a[4];
        {
            float bb = bd1[c1];
            #pragma unroll
            for (int j = 0; j < 4; j++) a[j] = bb;
            #pragma unroll
            for (int i = 0; i < 16; i++) {
                float w = wd1[i*NH + c1];
                #pragma unroll
                for (int j = 0; j < 4; j++)
                    a[j] = fmaf(xi[(base+j)*16 + i], w, a[j]);
            }
        }
        float ss[4], qq[4];
        #pragma unroll
        for (int j = 0; j < 4; j++) { ss[j] = a[j]; qq[j] = a[j]*a[j]; }
        #pragma unroll
        for (int off = 16; off > 0; off >>= 1) {
            #pragma unroll
            for (int j = 0; j < 4; j++) {
                ss[j] += __shfl_xor_sync(0xffffffff, ss[j], off);
                qq[j] += __shfl_xor_sync(0xffffffff, qq[j], off);
            }
        }
        if (lane == 0) {
            #pragma unroll
            for (int j = 0; j < 4; j++) { redS[w8*4+j] = ss[j]; redQ[w8*4+j] = qq[j]; }
        }
        __syncthreads();

        float g = lng[c1], be = lnb[c1];
        int gw = (base == 0) ? 0 : 4;
        {
            float4 hv; float* hp = (float*)&hv;
            #pragma unroll
            for (int j = 0; j < 4; j++) {
                float S = redS[(gw+0)*4+j] + redS[(gw+1)*4+j]
                        + redS[(gw+2)*4+j] + redS[(gw+3)*4+j];
                float Q = redQ[(gw+0)*4+j] + redQ[(gw+1)*4+j]
                        + redQ[(gw+2)*4+j] + redQ[(gw+3)*4+j];
                float mu  = S * (1.f/128.f);
                float var = Q * (1.f/128.f) - mu*mu;
                float ln = (a[j] - mu) * rsqrtf(var + 1e-5f) * g + be;
                hp[j] = fmaxf(ln, 0.f);
            }
            *(float4*)&htm[c1*8 + base] = hv;
        }
        __syncthreads();

        // GEMM2, packed row pairs
        {
            float bb = bd2[c1];
            u64 bb2 = pack2(bb, bb);
            u64 a01 = bb2, a23 = bb2;
            #pragma unroll 8
            for (int p = 0; p < NH; p++) {
                float w = wd2[p*NH + c1];
                u64 w2p = pack2(w, w);
                ulonglong2 h = *(const ulonglong2*)&htm[p*8 + base];
                a01 = fma2(h.x, w2p, a01);
                a23 = fma2(h.y, w2p, a23);
            }
            float o0,o1,o2,o3;
            unpack2(a01, o0, o1); unpack2(a23, o2, o3);
            qd_out[(row0+base+0)*NH + c1] = o0;
            qd_out[(row0+base+1)*NH + c1] = o1;
            qd_out[(row0+base+2)*NH + c1] = o2;
            qd_out[(row0+base+3)*NH + c1] = o3;
        }
    }

    // ===== pre-barrier: load + convert value/mask -> mv/mf =====
    __syncthreads();     // stage-1 smem reads done before any mv/mf reuse
    {
        const float4* v4 = (const float4*)(value + b*SK*DIM);
        const int4*   m4 = (const int4*)  (mask  + b*SK*DIM);
        float4* mv4 = (float4*)mv;
        float4* mf4 = (float4*)mf;
        #pragma unroll
        for (int j = 0; j < 4; j++) {
            int idx = t + j*256;               // 1024 float4s
            int4 mm = m4[idx]; float4 vv = v4[idx];
            float4 av, af;
            av.x = mm.x ? vv.x : 0.f;  af.x = mm.x ? 1.f : 0.f;
            av.y = mm.y ? vv.y : 0.f;  af.y = mm.y ? 1.f : 0.f;
            av.z = mm.z ? vv.z : 0.f;  af.z = mm.z ? 1.f : 0.f;
            av.w = mm.w ? vv.w : 0.f;  af.w = mm.w ? 1.f : 0.f;
            mv4[idx] = av; mf4[idx] = af;
        }
    }

    // ================= grid barrier =================
    __threadfence();
    __syncthreads();
    if (t == 0) {
        unsigned long long ticket = atomicAdd(&g_bar, 1ULL);
        unsigned long long target = (ticket >> 8) * 256ULL + 256ULL;
        volatile unsigned long long* vb = &g_bar;
        while (*vb < target) { __nanosleep(64); }
        __threadfence();
    }
    __syncthreads();

    // ================= Stage 2: attn + out epilogue =================
    // load ks/qs (proj-dependent; via L2 to dodge stale-L1 across barrier)
    {
        const float4* gk4 = (const float4*)g_k;
        float4* ks4 = (float4*)ks;
        #pragma unroll
        for (int j = 0; j < 8; j++) {
            int idx = t + j*256;               // 2048 float4s
            ks4[idx] = __ldcg(&gk4[b*2048 + idx]);
        }
        qs[t] = __ldcg(&g_q[(b*SQ + q0 + (t>>6))*EV + (t&63)]);
    }
    __syncthreads();

    const float scale = 0.35355339059327373f;   // 1/sqrt(8)

    // phase A: scores + softmax weights (R14 structure: batched dots,
    // shuffle max, batched exps). warp = head mapping (ks dedup 4x).
    {
        int h  = t >> 5;
        int q  = (t >> 3) & 3;
        int kq = t & 7;
        int vr = q*8 + h;             // es row convention unchanged
        int kbase = kq * 16;
        float4 q0r = *(const float4*)&qs[q*EV + h*DKd];
        float4 q1r = *(const float4*)&qs[q*EV + h*DKd + 4];
        u64 qp0 = pack2(q0r.x, q0r.y);
        u64 qp1 = pack2(q0r.z, q0r.w);
        u64 qp2 = pack2(q1r.x, q1r.y);
        u64 qp3 = pack2(q1r.z, q1r.w);

        float s[16];
        #pragma unroll
        for (int i = 0; i < 16; i++) {
            const ulonglong2* kp = (const ulonglong2*)&ks[(kbase+i)*EV + h*DKd];
            ulonglong2 k0 = kp[0], k1 = kp[1];
            u64 a2 = fma2(qp0, k0.x, 0ULL);
            a2 = fma2(qp1, k0.y, a2);
            a2 = fma2(qp2, k1.x, a2);
            a2 = fma2(qp3, k1.y, a2);
            float lo, hi;
            unpack2(a2, lo, hi);
            s[i] = lo + hi;
        }
        float mx = s[0];
        #pragma unroll
        for (int i = 1; i < 16; i++) mx = fmaxf(mx, s[i]);
        mx = fmaxf(mx, __shfl_xor_sync(0xffffffff, mx, 1));
        mx = fmaxf(mx, __shfl_xor_sync(0xffffffff, mx, 2));
        mx = fmaxf(mx, __shfl_xor_sync(0xffffffff, mx, 4));
        float msc = mx * scale;
        #pragma unroll
        for (int i4 = 0; i4 < 4; i4++) {
            float4 ev;
            ev.x = __expf(fmaf(s[i4*4+0], scale, -msc));
            ev.y = __expf(fmaf(s[i4*4+1], scale, -msc));
            ev.z = __expf(fmaf(s[i4*4+2], scale, -msc));
            ev.w = __expf(fmaf(s[i4*4+3], scale, -msc));
            *(float4*)&es[vr*ESS + kbase + i4*4] = ev;
        }
    }
    __syncthreads();   // ks reads done -> xs overlay (on ks) is safe below

    // phase B: num/den accumulate, packed. vr 0..31, dq 0..7 (4 d each)
    float4 xo;
    int vrB = t >> 3, dqB = t & 7;
    {
        u64 n01 = 0, n23 = 0, d01 = 0, d23 = 0;
        const ulonglong2* mv2 = (const ulonglong2*)mv;
        const ulonglong2* mf2 = (const ulonglong2*)mf;
        const float4* ep4 = (const float4*)&es[vrB*ESS];
        #pragma unroll 4
        for (int k4 = 0; k4 < SK/4; k4++) {
            float4 e4 = ep4[k4];
            #pragma unroll
            for (int j = 0; j < 4; j++) {
                float e = (j==0) ? e4.x : (j==1) ? e4.y : (j==2) ? e4.z : e4.w;
                int k = k4*4 + j;
                u64 e2 = pack2(e, e);
                ulonglong2 v = mv2[k*8 + dqB];
                ulonglong2 m = mf2[k*8 + dqB];
                n01 = fma2(e2, v.x, n01);
                n23 = fma2(e2, v.y, n23);
                d01 = fma2(e2, m.x, d01);
                d23 = fma2(e2, m.y, d23);
            }
        }
        float n0,n1,n2,n3, dd0,dd1,dd2,dd3;
        unpack2(n01, n0, n1); unpack2(n23, n2, n3);
        unpack2(d01, dd0, dd1); unpack2(d23, dd2, dd3);
        xo.x = __fdividef(n0, dd0); xo.y = __fdividef(n1, dd1);
        xo.z = __fdividef(n2, dd2); xo.w = __fdividef(n3, dd3);
    }
    {
        int q = vrB >> 3, h = vrB & 7;
        *(float4*)&xs[q*256 + h*DIM + dqB*4] = xo;
    }
    __syncthreads();

    // epilogue: y[q][c] = sum_p xs[q][p] * wo[p][c] + bo[c]
    // 2 independent chains over p-halves, unroll 32 -> deep wo-LDG pipeline.
    {
        int cp   = (t & 63) * 2;
        int qsel = t >> 6;            // 0..3
        int cph  = cp >> 1;
        const float* xp = &xs[qsel*256];
        const u64* wo2 = (const u64*)wo;   // index p*64 + cph
        u64 acc0 = pack2(bo[cp], bo[cp+1]);
        u64 acc1 = 0;
        #pragma unroll 32
        for (int p = 0; p < 128; p++) {
            u64 w0 = wo2[p*64 + cph];
            u64 w1v = wo2[(p+128)*64 + cph];
            acc0 = fma2(pack2(xp[p],     xp[p]),     w0,  acc0);
            acc1 = fma2(pack2(xp[p+128], xp[p+128]), w1v, acc1);
        }
        u64 s = add2(acc0, acc1);
        float r0v, r1v;
        unpack2(s, r0v, r1v);
        float2 o; o.x = r0v; o.y = r1v;
        *(float2*)&y_out[(b*SQ + q0 + qsel)*NH + cp] = o;
    }
}

// ---------------------------------------------------------------------------
extern "C" void kernel_launch(void* const* d_in, const int* in_sizes, int n_in,
                              void* d_out, int out_size)
{
    bool dictOrder = (in_sizes[4] == Bn*SK*DIM);

    const float *qv, *kv, *val, *imp, *w1, *b1, *w2, *wq, *bq, *wk, *bk,
                *wo, *bo, *wd1, *bd1, *lng, *lnb, *wd2, *bd2;
    const int* mask;

    if (dictOrder) {
        qv  = (const float*)d_in[0];  kv  = (const float*)d_in[1];
        val = (const float*)d_in[2];  imp = (const float*)d_in[3];
        mask= (const int*)  d_in[4];
        w1  = (const float*)d_in[5];  b1  = (const float*)d_in[6];
        w2  = (const float*)d_in[7];
        wq  = (const float*)d_in[8];  bq  = (const float*)d_in[9];
        wk  = (const float*)d_in[10]; bk  = (const float*)d_in[11];
        wo  = (const float*)d_in[12]; bo  = (const float*)d_in[13];
        wd1 = (const float*)d_in[14]; bd1 = (const float*)d_in[15];
        lng = (const float*)d_in[16]; lnb = (const float*)d_in[17];
        wd2 = (const float*)d_in[18]; bd2 = (const float*)d_in[19];
    } else {
        qv  = (const float*)d_in[0];  kv  = (const float*)d_in[1];
        val = (const float*)d_in[2];  imp = (const float*)d_in[3];
        w1  = (const float*)d_in[4];  b1  = (const float*)d_in[5];
        w2  = (const float*)d_in[6];
        wq  = (const float*)d_in[7];  bq  = (const float*)d_in[8];
        wk  = (const float*)d_in[9];  bk  = (const float*)d_in[10];
        wo  = (const float*)d_in[11]; bo  = (const float*)d_in[12];
        wd1 = (const float*)d_in[13]; bd1 = (const float*)d_in[14];
        lng = (const float*)d_in[15]; lnb = (const float*)d_in[16];
        wd2 = (const float*)d_in[17]; bd2 = (const float*)d_in[18];
        mask= (const int*)  d_in[19];
    }

    float* y  = (float*)d_out;                       // [8,128,128]
    float* qd = (float*)d_out + Bn*SQ*NH;            // [8,128,128]

    cudaFuncSetAttribute(mega_kernel,
                         cudaFuncAttributeMaxDynamicSharedMemorySize,
                         20992 * sizeof(float));

    mega_kernel<<<256, 256, 20992 * sizeof(float)>>>(
        qv, kv, val, mask, w1, b1, w2, wq, bq, wk, bk, wo, bo,
        imp, wd1, bd1, lng, lnb, wd2, bd2, y, qd);
}